// round 8
// baseline (speedup 1.0000x reference)
#include <cuda_runtime.h>
#include <stdint.h>

// MaskPyramids single-pass, single-launch. Each thread chunk = 16 contiguous
// floats (4x STG.128); level decode done ONCE per chunk; ~97% of chunks take
// a pure zero-store fast path. Odd-parity instances (row stride 53294 % 4 = 2)
// shift chunks by +2 elements so all bulk stores stay 16B-aligned; a spare
// slot per level writes the 2-float head and 14-float tail.
//
// grid = (4, 512). chunk ids: [0,2500) -> level 200, [2500,3125) -> level 100,
// bx==3 additionally runs the scalar tail levels (50/25/13).
//
// Rounding replicates XLA's div->reciprocal-mul rewrite (verified exact R3):
//   rint( fl( fl(p * fl(1/200)) * H ) ), all f32 RN-even.

#define N_INST   512
#define G        28
#define CTRK     13
#define PER_INST 53294   // 40000 + 10000 + 2500 + 625 + 169

__device__ __forceinline__ float mval(const float* __restrict__ mask,
                                      int si, int sj) {
    return ((unsigned)si < (unsigned)G && (unsigned)sj < (unsigned)G)
               ? __ldg(&mask[si * G + sj]) : 0.0f;
}

// One 16-float chunk at level-local offset `off` (16B-aligned globally).
template<int H, int BASE>
__device__ __forceinline__ void chunk16(int off, int c0, int b0,
                                        const float* __restrict__ mask,
                                        float* __restrict__ outrow) {
    const int row = off / H;            // compile-time magic div
    const int col = off - row * H;
    const int si  = row + c0;
    const int n0  = H - col;            // elems before row break
    const bool straddle = (n0 < 16);

    float v[16];
    #pragma unroll
    for (int e = 0; e < 16; e++) v[e] = 0.0f;

    const int d = col - b0;
    const bool touch0 = ((unsigned)si < (unsigned)G) && (d > -16) && (d < G);
    const bool touch1 = straddle && ((unsigned)(si + 1) < (unsigned)G);

    if (touch0 || touch1) {             // rare (~3%): per-element gather
        #pragma unroll
        for (int e = 0; e < 16; e++) {
            int c = col + e;
            int r = si;
            if (c >= H) { c -= H; r += 1; }
            v[e] = mval(mask, r, c - b0);
        }
    }

    float4* dst = reinterpret_cast<float4*>(outrow + BASE + off);
    dst[0] = make_float4(v[0],  v[1],  v[2],  v[3]);
    dst[1] = make_float4(v[4],  v[5],  v[6],  v[7]);
    dst[2] = make_float4(v[8],  v[9],  v[10], v[11]);
    dst[3] = make_float4(v[12], v[13], v[14], v[15]);
}

// Odd-parity head (elems 0,1) + tail (last 14 elems) of one level.
template<int H, int BASE>
__device__ __forceinline__ void headtail(int c0, int b0,
                                         const float* __restrict__ mask,
                                         float* __restrict__ outrow) {
    float2 h;                            // row 0, cols 0,1  (8B-aligned)
    h.x = mval(mask, c0, 0 - b0);
    h.y = mval(mask, c0, 1 - b0);
    *reinterpret_cast<float2*>(outrow + BASE) = h;

    float t[14];                         // row H-1, cols H-14..H-1
    #pragma unroll
    for (int e = 0; e < 14; e++)
        t[e] = mval(mask, H - 1 + c0, H - 14 + e - b0);
    float4* d4 = reinterpret_cast<float4*>(outrow + BASE + H * H - 14);
    d4[0] = make_float4(t[0], t[1], t[2],  t[3]);
    d4[1] = make_float4(t[4], t[5], t[6],  t[7]);
    d4[2] = make_float4(t[8], t[9], t[10], t[11]);
    *reinterpret_cast<float2*>(outrow + BASE + H * H - 2) =
        make_float2(t[12], t[13]);
}

template<int H, int BASE, int N>
__device__ __forceinline__ void do_tail_level(float pp0, float pp1,
                                              const float* __restrict__ mask,
                                              float* __restrict__ outrow) {
    const int lh = (int)rintf(__fmul_rn(pp0, (float)H));
    const int lw = (int)rintf(__fmul_rn(pp1, (float)H));
    const int c0 = CTRK - lh;
    const int b0 = lw - CTRK;
    for (int idx = threadIdx.x; idx < N; idx += 256) {
        const int row = idx / H;        // compile-time magic div
        const int col = idx - row * H;
        outrow[BASE + idx] = mval(mask, row + c0, col - b0);
    }
}

__global__ void __launch_bounds__(256)
fused_kernel(const int* __restrict__ pos,
             const float* __restrict__ mask,
             float* __restrict__ out) {
    const int inst = blockIdx.y;
    const int bx   = blockIdx.x;
    const int tid  = threadIdx.x;

    const float recip = 0.005f;  // fl(1/200) bit-exactly
    const float pp0 = __fmul_rn((float)__ldg(&pos[2 * inst + 0]), recip);
    const float pp1 = __fmul_rn((float)__ldg(&pos[2 * inst + 1]), recip);

    // window centers for levels 200 and 100
    const int c0_200 = CTRK - (int)rintf(__fmul_rn(pp0, 200.f));
    const int b0_200 = (int)rintf(__fmul_rn(pp1, 200.f)) - CTRK;
    const int c0_100 = CTRK - (int)rintf(__fmul_rn(pp0, 100.f));
    const int b0_100 = (int)rintf(__fmul_rn(pp1, 100.f)) - CTRK;

    float* outrow = out + inst * PER_INST;
    const bool odd = (inst & 1) != 0;

    #pragma unroll
    for (int k = 0; k < 4; k++) {
        const int id = bx * 1024 + k * 256 + tid;
        if (id < 2500) {
            if (!odd)
                chunk16<200, 0>(id * 16, c0_200, b0_200, mask, outrow);
            else if (id < 2499)
                chunk16<200, 0>(2 + id * 16, c0_200, b0_200, mask, outrow);
            else
                headtail<200, 0>(c0_200, b0_200, mask, outrow);
        } else if (id < 3125) {
            const int j = id - 2500;
            if (!odd)
                chunk16<100, 40000>(j * 16, c0_100, b0_100, mask, outrow);
            else if (j < 624)
                chunk16<100, 40000>(2 + j * 16, c0_100, b0_100, mask, outrow);
            else
                headtail<100, 40000>(c0_100, b0_100, mask, outrow);
        }
    }

    if (bx == 3) {
        do_tail_level<50, 50000, 2500>(pp0, pp1, mask, outrow);
        do_tail_level<25, 52500, 625>(pp0, pp1, mask, outrow);
        do_tail_level<13, 53125, 169>(pp0, pp1, mask, outrow);
    }
}

extern "C" void kernel_launch(void* const* d_in, const int* in_sizes, int n_in,
                              void* d_out, int out_size) {
    const int*   pos  = (const int*)d_in[0];      // int32 [512, 2]
    const float* mask = (const float*)d_in[1];    // float32 [28, 28]
    float*       out  = (float*)d_out;            // float32 [512, 53294]

    fused_kernel<<<dim3(4, N_INST), 256>>>(pos, mask, out);
}

// round 9
// speedup vs baseline: 1.5417x; 1.5417x over previous
#include <cuda_runtime.h>
#include <stdint.h>

// MaskPyramids single-pass, single-launch, warp-contiguous STG.128 stores.
// out[inst, :] = concat over 5 levels of a 28x28 gaussian window placed at
// round(pos/200*H) in each HxH grid; everything else zero.
//
// grid = (14, 512): bx 0-9 -> level 200x200, bx 10-12 -> level 100x100,
// bx 13 -> levels 50/25/13 (scalar tail). Each thread: 4 float4 chunks,
// warp-contiguous (lane stride 16B -> perfectly coalesced 512B/warp-instr).
// Odd instances (row stride 53294 % 4 == 2) shift coverage by +2 elements so
// all bulk stores stay 16B-aligned STG.128; one spare slot writes the 2-float
// head and 2-float tail; f4s straddling a row break (col == H-2) take a tiny
// gather path.
//
// Rounding replicates XLA's div->reciprocal-mul rewrite (verified exact R3):
//   rint( fl( fl(p * fl(1/200)) * H ) ), all f32 RN-even.

#define N_INST   512
#define G        28
#define CTRK     13
#define PER_INST 53294   // 40000 + 10000 + 2500 + 625 + 169

__device__ __forceinline__ float mval(const float* __restrict__ mask,
                                      int si, int sj) {
    return ((unsigned)si < (unsigned)G && (unsigned)sj < (unsigned)G)
               ? __ldg(&mask[si * G + sj]) : 0.0f;
}

template<int H, int BASE, bool ODD>
__device__ __forceinline__ void do_level(int chunk, int c0, int b0,
                                         bool headcols,
                                         const float* __restrict__ mask,
                                         float* __restrict__ outrow) {
    constexpr int NELEM = H * H;
    constexpr int SHIFT = ODD ? 2 : 0;
    constexpr int NF4   = (NELEM - SHIFT) / 4;  // 10000/9999, 2500/2499
    float* outbase = outrow + BASE;

    #pragma unroll
    for (int k = 0; k < 4; k++) {
        const int f4 = chunk * 1024 + k * 256 + threadIdx.x;
        if (f4 < NF4) {
            const int off = SHIFT + f4 * 4;
            const int row = off / H;            // compile-time magic div
            const int col = off - row * H;
            const int si  = row + c0;
            const int sj  = col - b0;
            const bool strad = ODD && (col > H - 4);   // col == H-2 only
            const bool need  = ((unsigned)si < (unsigned)G && sj > -4 && sj < G)
                            || (strad && (unsigned)(si + 1) < (unsigned)G && headcols);
            float4 v = make_float4(0.f, 0.f, 0.f, 0.f);
            if (need) {
                if (!ODD || !strad) {
                    const float* mrow = mask + si * G;
                    if ((unsigned)(sj + 0) < (unsigned)G) v.x = __ldg(&mrow[sj + 0]);
                    if ((unsigned)(sj + 1) < (unsigned)G) v.y = __ldg(&mrow[sj + 1]);
                    if ((unsigned)(sj + 2) < (unsigned)G) v.z = __ldg(&mrow[sj + 2]);
                    if ((unsigned)(sj + 3) < (unsigned)G) v.w = __ldg(&mrow[sj + 3]);
                } else {
                    // elements: (si, H-2), (si, H-1), (si+1, 0), (si+1, 1)
                    v.x = mval(mask, si,     H - 2 - b0);
                    v.y = mval(mask, si,     H - 1 - b0);
                    v.z = mval(mask, si + 1, 0 - b0);
                    v.w = mval(mask, si + 1, 1 - b0);
                }
            }
            *reinterpret_cast<float4*>(outbase + off) = v;   // STG.128, aligned
        } else if (ODD && f4 == NF4) {
            // head: elements 0,1 (row 0); tail: elements NELEM-2, NELEM-1
            // (SHIFT + 4*NF4 == NELEM - 2 for both H=200 and H=100)
            float2 h;
            h.x = mval(mask, c0, 0 - b0);
            h.y = mval(mask, c0, 1 - b0);
            *reinterpret_cast<float2*>(outbase) = h;
            float2 t;
            t.x = mval(mask, H - 1 + c0, H - 2 - b0);
            t.y = mval(mask, H - 1 + c0, H - 1 - b0);
            *reinterpret_cast<float2*>(outbase + NELEM - 2) = t;
        }
    }
}

template<int H, int BASE, int N>
__device__ __forceinline__ void do_tail_level(float pp0, float pp1,
                                              const float* __restrict__ mask,
                                              float* __restrict__ outrow) {
    const int lh = (int)rintf(__fmul_rn(pp0, (float)H));
    const int lw = (int)rintf(__fmul_rn(pp1, (float)H));
    const int c0 = CTRK - lh;
    const int b0 = lw - CTRK;
    for (int idx = threadIdx.x; idx < N; idx += 256) {
        const int row = idx / H;                // compile-time magic div
        const int col = idx - row * H;
        outrow[BASE + idx] = mval(mask, row + c0, col - b0);
    }
}

__global__ void __launch_bounds__(256)
fused_kernel(const int* __restrict__ pos,
             const float* __restrict__ mask,
             float* __restrict__ out) {
    const int inst = blockIdx.y;
    const int bx   = blockIdx.x;

    const float recip = 0.005f;  // fl(1/200) bit-exactly
    const float pp0 = __fmul_rn((float)__ldg(&pos[2 * inst + 0]), recip);
    const float pp1 = __fmul_rn((float)__ldg(&pos[2 * inst + 1]), recip);

    float* outrow = out + inst * PER_INST;
    const bool odd = (inst & 1) != 0;

    if (bx < 10) {
        const int c0 = CTRK - (int)rintf(__fmul_rn(pp0, 200.f));
        const int b0 = (int)rintf(__fmul_rn(pp1, 200.f)) - CTRK;
        const bool hc = (b0 >= -(G - 1)) && (b0 <= 1);
        if (!odd) do_level<200, 0, false>(bx, c0, b0, hc, mask, outrow);
        else      do_level<200, 0, true >(bx, c0, b0, hc, mask, outrow);
    } else if (bx < 13) {
        const int c0 = CTRK - (int)rintf(__fmul_rn(pp0, 100.f));
        const int b0 = (int)rintf(__fmul_rn(pp1, 100.f)) - CTRK;
        const bool hc = (b0 >= -(G - 1)) && (b0 <= 1);
        if (!odd) do_level<100, 40000, false>(bx - 10, c0, b0, hc, mask, outrow);
        else      do_level<100, 40000, true >(bx - 10, c0, b0, hc, mask, outrow);
    } else {
        do_tail_level<50, 50000, 2500>(pp0, pp1, mask, outrow);
        do_tail_level<25, 52500, 625>(pp0, pp1, mask, outrow);
        do_tail_level<13, 53125, 169>(pp0, pp1, mask, outrow);
    }
}

extern "C" void kernel_launch(void* const* d_in, const int* in_sizes, int n_in,
                              void* d_out, int out_size) {
    const int*   pos  = (const int*)d_in[0];      // int32 [512, 2]
    const float* mask = (const float*)d_in[1];    // float32 [28, 28]
    float*       out  = (float*)d_out;            // float32 [512, 53294]

    fused_kernel<<<dim3(14, N_INST), 256>>>(pos, mask, out);
}

// round 10
// speedup vs baseline: 1.6616x; 1.0777x over previous
#include <cuda_runtime.h>
#include <stdint.h>

// MaskPyramids single-pass, single-launch, STORE-FIRST strategy:
// pass 1 stores zeros unconditionally (addresses independent of any load, so
// stores issue at full rate); pass 2 overwrites the <=784 window elements per
// (inst, level) with mask values (same-thread WAW is program-ordered).
//
// grid = (14, 512): bx 0-9 -> level 200x200, bx 10-12 -> level 100x100,
// bx 13 -> levels 50/25/13 (scalar tail). Each thread: 4 warp-contiguous
// float4 chunks. Even instances use STG.128; odd (row stride 53294 % 4 == 2)
// use 2x STG.64.
//
// Rounding replicates XLA's div->reciprocal-mul rewrite (verified exact R3):
//   rint( fl( fl(p * fl(1/200)) * H ) ), all f32 RN-even.

#define N_INST   512
#define G        28
#define CTRK     13
#define PER_INST 53294   // 40000 + 10000 + 2500 + 625 + 169

__device__ __forceinline__ float mval(const float* __restrict__ mask,
                                      int si, int sj) {
    return ((unsigned)si < (unsigned)G && (unsigned)sj < (unsigned)G)
               ? __ldg(&mask[si * G + sj]) : 0.0f;
}

template<int H, int BASE>
__device__ __forceinline__ void do_level(int chunk, float pp0, float pp1,
                                         bool even,
                                         const float* __restrict__ mask,
                                         float* __restrict__ outrow) {
    constexpr int NF4 = H * H / 4;
    float* base = outrow + BASE;

    // ---- pass 1: unconditional zero stores (no data dependencies) ----
    #pragma unroll
    for (int k = 0; k < 4; k++) {
        const int f4 = chunk * 1024 + k * 256 + threadIdx.x;
        if (f4 < NF4) {
            float* dst = base + f4 * 4;
            if (even) {
                *reinterpret_cast<float4*>(dst) =
                    make_float4(0.f, 0.f, 0.f, 0.f);
            } else {
                reinterpret_cast<float2*>(dst)[0] = make_float2(0.f, 0.f);
                reinterpret_cast<float2*>(dst)[1] = make_float2(0.f, 0.f);
            }
        }
    }

    // ---- window center (depends on pos LDG; hidden under pass-1 stores) ----
    const int lh = (int)rintf(__fmul_rn(pp0, (float)H));
    const int lw = (int)rintf(__fmul_rn(pp1, (float)H));
    const int c0 = CTRK - lh;          // si = row + c0
    const int b0 = lw - CTRK;          // sj = col - b0

    // ---- pass 2: sparse overwrite of window elements (~3% of chunks) ----
    #pragma unroll
    for (int k = 0; k < 4; k++) {
        const int f4 = chunk * 1024 + k * 256 + threadIdx.x;
        if (f4 < NF4) {
            const int off = f4 * 4;
            const int row = off / H;           // compile-time magic div
            const int col = off - row * H;     // H%4==0: no row straddle
            const int si  = row + c0;
            const int sj  = col - b0;
            if ((unsigned)si < (unsigned)G && sj > -4 && sj < G) {
                const float* mrow = mask + si * G;
                #pragma unroll
                for (int e = 0; e < 4; e++) {
                    const int s = sj + e;
                    if ((unsigned)s < (unsigned)G)
                        base[off + e] = __ldg(&mrow[s]);
                }
            }
        }
    }
}

template<int H, int BASE, int N>
__device__ __forceinline__ void do_tail_level(float pp0, float pp1,
                                              const float* __restrict__ mask,
                                              float* __restrict__ outrow) {
    const int lh = (int)rintf(__fmul_rn(pp0, (float)H));
    const int lw = (int)rintf(__fmul_rn(pp1, (float)H));
    const int c0 = CTRK - lh;
    const int b0 = lw - CTRK;
    for (int idx = threadIdx.x; idx < N; idx += 256) {
        const int row = idx / H;               // compile-time magic div
        const int col = idx - row * H;
        outrow[BASE + idx] = mval(mask, row + c0, col - b0);
    }
}

__global__ void __launch_bounds__(256)
fused_kernel(const int* __restrict__ pos,
             const float* __restrict__ mask,
             float* __restrict__ out) {
    const int inst = blockIdx.y;
    const int bx   = blockIdx.x;

    const float recip = 0.005f;  // fl(1/200) bit-exactly
    const float pp0 = __fmul_rn((float)__ldg(&pos[2 * inst + 0]), recip);
    const float pp1 = __fmul_rn((float)__ldg(&pos[2 * inst + 1]), recip);

    float* outrow = out + inst * PER_INST;
    const bool even = ((inst & 1) == 0);   // row stride 53294 % 4 == 2

    if (bx < 10) {
        do_level<200, 0>(bx, pp0, pp1, even, mask, outrow);
    } else if (bx < 13) {
        do_level<100, 40000>(bx - 10, pp0, pp1, even, mask, outrow);
    } else {
        do_tail_level<50, 50000, 2500>(pp0, pp1, mask, outrow);
        do_tail_level<25, 52500, 625>(pp0, pp1, mask, outrow);
        do_tail_level<13, 53125, 169>(pp0, pp1, mask, outrow);
    }
}

extern "C" void kernel_launch(void* const* d_in, const int* in_sizes, int n_in,
                              void* d_out, int out_size) {
    const int*   pos  = (const int*)d_in[0];      // int32 [512, 2]
    const float* mask = (const float*)d_in[1];    // float32 [28, 28]
    float*       out  = (float*)d_out;            // float32 [512, 53294]

    fused_kernel<<<dim3(14, N_INST), 256>>>(pos, mask, out);
}